// round 2
// baseline (speedup 1.0000x reference)
#include <cuda_runtime.h>
#include <cstdint>

#define BB 4
#define CC 128
#define NN 4096
#define BNN (BB*NN)   // 16384
#define THRESH2 256.0f

// ---------------- device scratch (no allocations allowed) ----------------
__device__ float g_xe[(size_t)BNN*CC];     // 8 MB  fc output [b][n][c]
__device__ float g_edge[(size_t)BNN*CC];   // 8 MB  edge features
__device__ float g_vout[(size_t)BNN*CC];   // 8 MB  vert + residual, [b][n][c]
__device__ float g_sq[BNN];                // squared norms
__device__ float g_invdeg[BNN];            // 1/deg (0 if deg==0)
__device__ unsigned char g_mask[(size_t)BNN*NN]; // 64 MB incidence (symmetric)
__device__ float g_psum[256*CC];           // BN partial sums (deterministic)
__device__ float g_pss[256*CC];
__device__ float g_scale[CC];
__device__ float g_shift[CC];

// ---------------- squared norms: sq[b,n] = sum_c x[b,c,n]^2 ----------------
__global__ void sq_kernel(const float* __restrict__ x) {
    int t = blockIdx.x * blockDim.x + threadIdx.x;   // 0..BNN
    int b = t >> 12, n = t & (NN - 1);
    const float* xb = x + (size_t)b * CC * NN + n;
    float acc = 0.f;
    #pragma unroll
    for (int c = 0; c < CC; c++) { float v = xb[(size_t)c * NN]; acc += v * v; }
    g_sq[t] = acc;
}

// ---------------- FC: xe[b,n,d] = sum_c x[b,c,n]*W[d,c] + bias[d] ----------
__global__ void fc_kernel(const float* __restrict__ x,
                          const float* __restrict__ Wfc,
                          const float* __restrict__ bfc) {
    __shared__ float Xs[16][64];
    __shared__ float Ws[16][132];   // padded (write conflicts -> 2-way only)
    int bx = blockIdx.x;            // 256 blocks
    int b = bx >> 6;
    int n0 = (bx & 63) * 64;
    int tid = threadIdx.x;
    int warp = tid >> 5, lane = tid & 31;
    float acc[8][4] = {};
    const float* xb = x + (size_t)b * CC * NN;

    for (int c0 = 0; c0 < CC; c0 += 16) {
        #pragma unroll
        for (int k = 0; k < 4; k++) {
            int idx = tid + k * 256; int cc = idx >> 6, nn = idx & 63;
            Xs[cc][nn] = xb[(size_t)(c0 + cc) * NN + n0 + nn];
        }
        #pragma unroll
        for (int k = 0; k < 8; k++) {
            int idx = tid + k * 256; int d = idx >> 4, cc = idx & 15;
            Ws[cc][d] = Wfc[d * CC + c0 + cc];
        }
        __syncthreads();
        #pragma unroll
        for (int cc = 0; cc < 16; cc++) {
            float4 a0 = *(const float4*)&Xs[cc][warp * 8];
            float4 a1 = *(const float4*)&Xs[cc][warp * 8 + 4];
            float4 bv = *(const float4*)&Ws[cc][lane * 4];
            float av[8] = {a0.x,a0.y,a0.z,a0.w,a1.x,a1.y,a1.z,a1.w};
            #pragma unroll
            for (int i = 0; i < 8; i++) {
                acc[i][0] += av[i] * bv.x; acc[i][1] += av[i] * bv.y;
                acc[i][2] += av[i] * bv.z; acc[i][3] += av[i] * bv.w;
            }
        }
        __syncthreads();
    }
    float4 bias = *(const float4*)&bfc[lane * 4];
    #pragma unroll
    for (int i = 0; i < 8; i++) {
        int n = n0 + warp * 8 + i;
        float4 o = make_float4(acc[i][0] + bias.x, acc[i][1] + bias.y,
                               acc[i][2] + bias.z, acc[i][3] + bias.w);
        *(float4*)&g_xe[((size_t)b * NN + n) * CC + lane * 4] = o;
    }
}

// ---------------- incidence mask: mask[b,i,j] = (d2 < 256) -----------------
__global__ void mask_kernel(const float* __restrict__ x) {
    __shared__ float Xi[16][64];
    __shared__ float Xj[16][64];
    int b = blockIdx.z;
    int i0 = blockIdx.y * 64, j0 = blockIdx.x * 64;
    int tid = threadIdx.x;
    int ty = tid >> 4, tx = tid & 15;   // 16x16 threads, 4x4 micro
    const float* xb = x + (size_t)b * CC * NN;
    float acc[4][4] = {};

    for (int c0 = 0; c0 < CC; c0 += 16) {
        #pragma unroll
        for (int k = 0; k < 4; k++) {
            int idx = tid + k * 256; int cc = idx >> 6, nn = idx & 63;
            const float* row = xb + (size_t)(c0 + cc) * NN;
            Xi[cc][nn] = row[i0 + nn];
            Xj[cc][nn] = row[j0 + nn];
        }
        __syncthreads();
        #pragma unroll
        for (int cc = 0; cc < 16; cc++) {
            float4 av = *(const float4*)&Xi[cc][ty * 4];
            float4 bv = *(const float4*)&Xj[cc][tx * 4];
            float a[4] = {av.x, av.y, av.z, av.w};
            float bq[4] = {bv.x, bv.y, bv.z, bv.w};
            #pragma unroll
            for (int i = 0; i < 4; i++)
                #pragma unroll
                for (int j = 0; j < 4; j++)
                    acc[i][j] += a[i] * bq[j];
        }
        __syncthreads();
    }
    float sqi[4], sqj[4];
    #pragma unroll
    for (int i = 0; i < 4; i++) sqi[i] = g_sq[b * NN + i0 + ty * 4 + i];
    #pragma unroll
    for (int j = 0; j < 4; j++) sqj[j] = g_sq[b * NN + j0 + tx * 4 + j];
    #pragma unroll
    for (int i = 0; i < 4; i++) {
        uchar4 m;
        m.x = (sqi[i] + sqj[0] - 2.f * acc[i][0] < THRESH2) ? 1 : 0;
        m.y = (sqi[i] + sqj[1] - 2.f * acc[i][1] < THRESH2) ? 1 : 0;
        m.z = (sqi[i] + sqj[2] - 2.f * acc[i][2] < THRESH2) ? 1 : 0;
        m.w = (sqi[i] + sqj[3] - 2.f * acc[i][3] < THRESH2) ? 1 : 0;
        *(uchar4*)&g_mask[((size_t)(b * NN + i0 + ty * 4 + i)) * NN + j0 + tx * 4] = m;
    }
}

// ---------------- degree: inv_deg[row] = 1/rowsum(mask) --------------------
__global__ void deg_kernel() {
    int row = blockIdx.x;   // BNN blocks
    const unsigned int* m = (const unsigned int*)(g_mask + (size_t)row * NN);
    int tid = threadIdx.x;  // 128
    unsigned int s = 0u;
    #pragma unroll
    for (int k = 0; k < 8; k++) s = __dp4a(m[tid + k * 128], 0x01010101u, s);
    int si = (int)s;
    #pragma unroll
    for (int o = 16; o > 0; o >>= 1) si += __shfl_down_sync(0xffffffffu, si, o);
    __shared__ int ws[4];
    if ((tid & 31) == 0) ws[tid >> 5] = si;
    __syncthreads();
    if (tid == 0) {
        int d = ws[0] + ws[1] + ws[2] + ws[3];
        g_invdeg[row] = (d > 0) ? 1.0f / (float)d : 0.0f;
    }
}

// ------- propagation: out[i,:] = invdeg[i]*sum_j mask[i,j]*in[j,:] ---------
// pass 1: in=g_xe  -> out=g_edge
// pass 2: in=g_edge-> out=g_vout, plus residual xf (= x[b][c][n])
__global__ void prop_kernel(const float* __restrict__ x, int pass) {
    __shared__ float Ms[32][68];     // [jj][ii], padded & 16B-aligned rows
    __shared__ float Ins[32][CC];
    int b = blockIdx.y;
    int i0 = blockIdx.x * 64;
    int tid = threadIdx.x;
    int warp = tid >> 5, lane = tid & 31;
    const float* in  = (pass == 1) ? g_xe : g_edge;
    float*       out = (pass == 1) ? g_edge : g_vout;
    const unsigned char* mrow = g_mask + (size_t)(b * NN + i0) * NN;
    const float* inb = in + (size_t)b * NN * CC;
    float acc[8][4] = {};

    for (int j0 = 0; j0 < NN; j0 += 32) {
        #pragma unroll
        for (int k = 0; k < 4; k++) {          // 1024 float4 / 256 thr
            int idx = tid + k * 256;
            int jj = idx >> 5, c4 = idx & 31;
            *(float4*)&Ins[jj][c4 * 4] =
                *(const float4*)&inb[(size_t)(j0 + jj) * CC + c4 * 4];
        }
        #pragma unroll
        for (int k = 0; k < 2; k++) {          // 512 uchar4 / 256 thr
            int idx = tid + k * 256;
            int ii = idx >> 3, j4 = idx & 7;
            uchar4 mv = *(const uchar4*)(mrow + (size_t)ii * NN + j0 + j4 * 4);
            Ms[j4 * 4 + 0][ii] = (float)mv.x;
            Ms[j4 * 4 + 1][ii] = (float)mv.y;
            Ms[j4 * 4 + 2][ii] = (float)mv.z;
            Ms[j4 * 4 + 3][ii] = (float)mv.w;
        }
        __syncthreads();
        #pragma unroll
        for (int jj = 0; jj < 32; jj++) {
            float4 a0 = *(const float4*)&Ms[jj][warp * 8];
            float4 a1 = *(const float4*)&Ms[jj][warp * 8 + 4];
            float4 bv = *(const float4*)&Ins[jj][lane * 4];
            float av[8] = {a0.x,a0.y,a0.z,a0.w,a1.x,a1.y,a1.z,a1.w};
            #pragma unroll
            for (int i = 0; i < 8; i++) {
                acc[i][0] += av[i] * bv.x; acc[i][1] += av[i] * bv.y;
                acc[i][2] += av[i] * bv.z; acc[i][3] += av[i] * bv.w;
            }
        }
        __syncthreads();
    }
    #pragma unroll
    for (int i = 0; i < 8; i++) {
        int n = i0 + warp * 8 + i;
        int gi = b * NN + n;
        float s = g_invdeg[gi];
        float4 o = make_float4(acc[i][0]*s, acc[i][1]*s, acc[i][2]*s, acc[i][3]*s);
        if (pass == 2) {
            const float* xb = x + (size_t)b * CC * NN + n;
            o.x += xb[(size_t)(lane * 4 + 0) * NN];
            o.y += xb[(size_t)(lane * 4 + 1) * NN];
            o.z += xb[(size_t)(lane * 4 + 2) * NN];
            o.w += xb[(size_t)(lane * 4 + 3) * NN];
        }
        *(float4*)&out[(size_t)gi * CC + lane * 4] = o;
    }
}

// ---------------- BN stats: deterministic two-stage reduction --------------
__global__ void stats_kernel() {
    int c = threadIdx.x;        // 128
    int blk = blockIdx.x;       // 256 blocks, 64 rows each
    int r0 = blk * 64;
    float s = 0.f, ss = 0.f;
    for (int r = 0; r < 64; r++) {
        float v = g_vout[(size_t)(r0 + r) * CC + c];
        s += v; ss += v * v;
    }
    g_psum[blk * CC + c] = s;
    g_pss [blk * CC + c] = ss;
}

__global__ void bnparam_kernel(const float* __restrict__ gamma,
                               const float* __restrict__ beta) {
    int c = threadIdx.x;
    float s = 0.f, ss = 0.f;
    for (int blk = 0; blk < 256; blk++) {
        s  += g_psum[blk * CC + c];
        ss += g_pss [blk * CC + c];
    }
    float m = s / (float)BNN;
    float var = ss / (float)BNN - m * m;
    float sc = gamma[c] * rsqrtf(var + 1e-5f);
    g_scale[c] = sc;
    g_shift[c] = beta[c] - m * sc;
}

// ---------------- BN apply + SiLU + [b,n,c] -> [b,c,n] transpose -----------
__global__ void apply_kernel(float* __restrict__ out) {
    __shared__ float tile[32][33];
    int b = blockIdx.z;
    int c0 = blockIdx.y * 32, n0 = blockIdx.x * 32;
    int tx = threadIdx.x, ty = threadIdx.y;   // 32 x 8
    #pragma unroll
    for (int k = 0; k < 4; k++) {
        int nl = ty + k * 8;
        tile[nl][tx] = g_vout[(size_t)(b * NN + n0 + nl) * CC + c0 + tx];
    }
    __syncthreads();
    #pragma unroll
    for (int k = 0; k < 4; k++) {
        int cl = ty + k * 8;
        int c = c0 + cl;
        float v = tile[tx][cl];
        float y = v * g_scale[c] + g_shift[c];
        float sig = 1.0f / (1.0f + expf(-y));
        out[((size_t)b * CC + c) * NN + n0 + tx] = y * sig;
    }
}

// ---------------------------------------------------------------------------
extern "C" void kernel_launch(void* const* d_in, const int* in_sizes, int n_in,
                              void* d_out, int out_size) {
    const float* x     = (const float*)d_in[0];   // [4,128,64,64]
    const float* Wfc   = (const float*)d_in[1];   // [128,128]
    const float* bfc   = (const float*)d_in[2];   // [128]
    const float* gamma = (const float*)d_in[3];   // [128]
    const float* beta  = (const float*)d_in[4];   // [128]
    float* out = (float*)d_out;                   // [4,128,64,64]

    sq_kernel<<<BNN / 256, 256>>>(x);
    fc_kernel<<<256, 256>>>(x, Wfc, bfc);
    mask_kernel<<<dim3(64, 64, BB), 256>>>(x);
    deg_kernel<<<BNN, 128>>>();
    prop_kernel<<<dim3(64, BB), 256>>>(x, 1);
    prop_kernel<<<dim3(64, BB), 256>>>(x, 2);
    stats_kernel<<<256, 128>>>();
    bnparam_kernel<<<1, 128>>>(gamma, beta);
    apply_kernel<<<dim3(NN / 32, CC / 32, BB), dim3(32, 8)>>>(out);
}

// round 4
// speedup vs baseline: 3.8001x; 3.8001x over previous
#include <cuda_runtime.h>
#include <cuda_bf16.h>
#include <cstdint>

#define BB 4
#define CC 128
#define NN 4096
#define BNN (BB*NN)   // 16384
#define THRESH2 256.0f

// ===================== device scratch (no allocs allowed) =====================
__device__ __align__(128) __nv_bfloat16 g_xsplit[(size_t)BNN*256];   // 8 MB  [b][n][hi128|lo128]
__device__ __align__(128) __nv_bfloat16 g_xebf [(size_t)BNN*CC];     // 4 MB  fc out [b][c][n]
__device__ __align__(128) __nv_bfloat16 g_edgebf[(size_t)BNN*CC];    // 4 MB  edge   [b][c][n]
__device__ __align__(128) __nv_bfloat16 g_maskbf[(size_t)BNN*NN];    // 128 MB mask  [b][i][j]
__device__ __align__(128) float g_vout[(size_t)BNN*CC];              // 8 MB  vert+res [b][c][n]
__device__ float g_sq[BNN];
__device__ float g_invdeg[BNN];
__device__ int   g_deg[BNN];
__device__ float g_psum[CC*BB];
__device__ float g_pss[CC*BB];
__device__ float g_scale[CC];
__device__ float g_shift[CC];

// ===================== PTX helpers (plain sm_103-safe) =====================
__device__ __forceinline__ uint32_t smem_u32(const void* p) {
    uint32_t a;
    asm("{ .reg .u64 t; cvta.to.shared.u64 t, %1; cvt.u32.u64 %0, t; }" : "=r"(a) : "l"(p));
    return a;
}
__device__ __forceinline__ void cpa16(uint32_t dst, const void* src) {
    asm volatile("cp.async.cg.shared.global [%0], [%1], 16;" :: "r"(dst), "l"(src));
}
#define CP_COMMIT() asm volatile("cp.async.commit_group;" ::: "memory")
#define CP_WAIT(n)  asm volatile("cp.async.wait_group %0;" :: "n"(n) : "memory")

__device__ __forceinline__ void ldsm_x4(uint32_t (&r)[4], uint32_t addr) {
    asm volatile("ldmatrix.sync.aligned.m8n8.x4.shared.b16 {%0,%1,%2,%3}, [%4];"
        : "=r"(r[0]), "=r"(r[1]), "=r"(r[2]), "=r"(r[3]) : "r"(addr));
}
__device__ __forceinline__ void ldsm_x2(uint32_t (&r)[2], uint32_t addr) {
    asm volatile("ldmatrix.sync.aligned.m8n8.x2.shared.b16 {%0,%1}, [%2];"
        : "=r"(r[0]), "=r"(r[1]) : "r"(addr));
}
__device__ __forceinline__ void mma16816(float (&d)[4], const uint32_t (&a)[4],
                                         const uint32_t (&bq)[2]) {
    asm volatile("mma.sync.aligned.m16n8k16.row.col.f32.bf16.bf16.f32 "
        "{%0,%1,%2,%3}, {%4,%5,%6,%7}, {%8,%9}, {%0,%1,%2,%3};"
        : "+f"(d[0]), "+f"(d[1]), "+f"(d[2]), "+f"(d[3])
        : "r"(a[0]), "r"(a[1]), "r"(a[2]), "r"(a[3]), "r"(bq[0]), "r"(bq[1]));
}

// ===================== small prep kernels =====================
__global__ void sq_kernel(const float* __restrict__ x) {
    int t = blockIdx.x * blockDim.x + threadIdx.x;
    int b = t >> 12, n = t & (NN - 1);
    const float* xb = x + (size_t)b * CC * NN + n;
    float acc = 0.f;
    #pragma unroll
    for (int c = 0; c < CC; c++) { float v = xb[(size_t)c * NN]; acc += v * v; }
    g_sq[t] = acc;
    g_deg[t] = 0;
}

// x [b][c][n] fp32 -> xsplit [b][n][hi128|lo128] bf16 (transpose + split)
__global__ void split_kernel(const float* __restrict__ x) {
    __shared__ float tile[32][33];
    int b = blockIdx.z, c0 = blockIdx.y * 32, n0 = blockIdx.x * 32;
    int tx = threadIdx.x, ty = threadIdx.y;       // 32 x 8
    #pragma unroll
    for (int k = 0; k < 4; k++) {
        int cl = ty + k * 8;
        tile[cl][tx] = x[((size_t)(b * CC + c0 + cl)) * NN + n0 + tx];
    }
    __syncthreads();
    #pragma unroll
    for (int k = 0; k < 4; k++) {
        int nl = ty + k * 8;
        float v = tile[tx][nl];
        __nv_bfloat16 h = __float2bfloat16(v);
        __nv_bfloat16 l = __float2bfloat16(v - __bfloat162float(h));
        size_t base = ((size_t)(b * NN + n0 + nl)) * 256;
        g_xsplit[base + c0 + tx]       = h;
        g_xsplit[base + 128 + c0 + tx] = l;
    }
}

// FC: xebf[b][d][n] = bf16( sum_c W[d][c] * x[b][c][n] + bias[d] )
__global__ void fc_kernel(const float* __restrict__ x,
                          const float* __restrict__ Wfc,
                          const float* __restrict__ bfc) {
    __shared__ float Xs[16][64];
    __shared__ float Ws[16][132];
    int b = blockIdx.y;
    int n0 = blockIdx.x * 64;
    int tid = threadIdx.x;
    int ty = tid >> 4, tx = tid & 15;
    float acc[8][4] = {};
    for (int c0 = 0; c0 < CC; c0 += 16) {
        #pragma unroll
        for (int k = 0; k < 4; k++) {
            int idx = tid + k * 256; int cc = idx >> 6, nn = idx & 63;
            Xs[cc][nn] = x[((size_t)(b * CC + c0 + cc)) * NN + n0 + nn];
        }
        #pragma unroll
        for (int k = 0; k < 8; k++) {
            int idx = tid + k * 256; int d = idx >> 4, cc = idx & 15;
            Ws[cc][d] = Wfc[d * CC + c0 + cc];
        }
        __syncthreads();
        #pragma unroll
        for (int cc = 0; cc < 16; cc++) {
            float4 a0 = *(const float4*)&Ws[cc][ty * 8];
            float4 a1 = *(const float4*)&Ws[cc][ty * 8 + 4];
            float4 bv = *(const float4*)&Xs[cc][tx * 4];
            float a[8] = {a0.x,a0.y,a0.z,a0.w,a1.x,a1.y,a1.z,a1.w};
            #pragma unroll
            for (int i = 0; i < 8; i++) {
                acc[i][0] += a[i] * bv.x; acc[i][1] += a[i] * bv.y;
                acc[i][2] += a[i] * bv.z; acc[i][3] += a[i] * bv.w;
            }
        }
        __syncthreads();
    }
    #pragma unroll
    for (int i = 0; i < 8; i++) {
        int d = ty * 8 + i;
        float bi = bfc[d];
        __nv_bfloat16 o[4];
        #pragma unroll
        for (int j = 0; j < 4; j++) o[j] = __float2bfloat16(acc[i][j] + bi);
        *(uint2*)&g_xebf[((size_t)(b * CC + d)) * NN + n0 + tx * 4] = *(uint2*)o;
    }
}

// ===================== mask via mma.sync (split-bf16, K=256) =====================
// 128x128 tile per CTA. smem: A 128x128 bf16 (stride 272B) | B same. 2 chunks of K=128.
#define MSK_TSTRIDE 272
#define MSK_TILE    (128*MSK_TSTRIDE)      // 34816
#define MSK_SMEM    (2*MSK_TILE)           // 69632
__global__ void __launch_bounds__(256, 2) mask_mma_kernel() {
    extern __shared__ char smem[];
    uint32_t sb = smem_u32(smem);
    int tid = threadIdx.x, lane = tid & 31, warp = tid >> 5;
    int wm = warp >> 2, wn = warp & 3;     // 2 x 4 warp grid
    int b = blockIdx.z, i0g = blockIdx.y * 128, j0g = blockIdx.x * 128;

    float acc[4][4][4] = {};
    for (int chunk = 0; chunk < 2; chunk++) {
        #pragma unroll
        for (int k = 0; k < 16; k++) {
            int id = tid + k * 256;            // 0..4095
            int t = id >> 11, rem = id & 2047;
            int r = rem >> 4, s = rem & 15;
            const __nv_bfloat16* src = g_xsplit
                + ((size_t)(b * NN + (t ? j0g : i0g) + r)) * 256 + chunk * 128 + s * 8;
            cpa16(sb + t * MSK_TILE + r * MSK_TSTRIDE + s * 16, src);
        }
        CP_COMMIT(); CP_WAIT(0);
        __syncthreads();
        #pragma unroll
        for (int ks = 0; ks < 8; ks++) {
            uint32_t af[4][4], bq[4][2];
            #pragma unroll
            for (int mf = 0; mf < 4; mf++)
                ldsm_x4(af[mf], sb + (wm*64 + mf*16 + (lane & 15)) * MSK_TSTRIDE
                                   + ks*32 + ((lane >> 4) << 4));
            #pragma unroll
            for (int nf = 0; nf < 4; nf++)
                ldsm_x2(bq[nf], sb + MSK_TILE + (wn*32 + nf*8 + (lane & 7)) * MSK_TSTRIDE
                                   + ks*32 + (((lane >> 3) & 1) << 4));
            #pragma unroll
            for (int mf = 0; mf < 4; mf++)
                #pragma unroll
                for (int nf = 0; nf < 4; nf++)
                    mma16816(acc[mf][nf], af[mf], bq[nf]);
        }
        __syncthreads();
    }

    // epilogue: threshold -> bf16 mask + degree counts
    #pragma unroll
    for (int mf = 0; mf < 4; mf++) {
        int r0 = wm*64 + mf*16 + (lane >> 2);
        int r1 = r0 + 8;
        float sqi0 = g_sq[b * NN + i0g + r0];
        float sqi1 = g_sq[b * NN + i0g + r1];
        int c0n = 0, c1n = 0;
        #pragma unroll
        for (int nf = 0; nf < 4; nf++) {
            int col = wn*32 + nf*8 + (lane & 3) * 2;
            float sqa = g_sq[b * NN + j0g + col];
            float sqb = g_sq[b * NN + j0g + col + 1];
            bool m00 = sqi0 + sqa - 2.f * acc[mf][nf][0] < THRESH2;
            bool m01 = sqi0 + sqb - 2.f * acc[mf][nf][1] < THRESH2;
            bool m10 = sqi1 + sqa - 2.f * acc[mf][nf][2] < THRESH2;
            bool m11 = sqi1 + sqb - 2.f * acc[mf][nf][3] < THRESH2;
            c0n += (int)m00 + (int)m01;
            c1n += (int)m10 + (int)m11;
            uint32_t p0 = (m00 ? 0x3F80u : 0u) | ((m01 ? 0x3F80u : 0u) << 16);
            uint32_t p1 = (m10 ? 0x3F80u : 0u) | ((m11 ? 0x3F80u : 0u) << 16);
            *(uint32_t*)&g_maskbf[((size_t)(b*NN + i0g + r0)) * NN + j0g + col] = p0;
            *(uint32_t*)&g_maskbf[((size_t)(b*NN + i0g + r1)) * NN + j0g + col] = p1;
        }
        c0n += __shfl_xor_sync(0xffffffffu, c0n, 1);
        c0n += __shfl_xor_sync(0xffffffffu, c0n, 2);
        c1n += __shfl_xor_sync(0xffffffffu, c1n, 1);
        c1n += __shfl_xor_sync(0xffffffffu, c1n, 2);
        if ((lane & 3) == 0) {
            atomicAdd(&g_deg[b * NN + i0g + r0], c0n);
            atomicAdd(&g_deg[b * NN + i0g + r1], c1n);
        }
    }
}

__global__ void invdeg_kernel() {
    int t = blockIdx.x * blockDim.x + threadIdx.x;
    int d = g_deg[t];
    g_invdeg[t] = (d > 0) ? 1.0f / (float)d : 0.0f;
}

// ===================== propagation via mma.sync, 3-stage cp.async =====================
// out[c][i] = invdeg[i] * sum_j feat[c][j]*mask[i][j]  (A=feat M=128, B=mask N=128, K=4096)
#define PRP_STRIDE 80
#define PRP_TILE   (128*PRP_STRIDE)        // 10240
#define PRP_STAGE  (2*PRP_TILE)            // 20480 (A then B)
#define PRP_SMEM   (3*PRP_STAGE)           // 61440
__device__ __forceinline__ void prop_load(uint32_t sb, int st, int j,
        const __nv_bfloat16* feat, const __nv_bfloat16* mbase, int b, int tid) {
    #pragma unroll
    for (int k = 0; k < 2; k++) {
        int id = tid + k * 256;            // 0..511
        int r = id >> 2, s = id & 3;
        cpa16(sb + st*PRP_STAGE + r*PRP_STRIDE + s*16,
              feat + ((size_t)(b * CC + r)) * NN + j + s * 8);
        cpa16(sb + st*PRP_STAGE + PRP_TILE + r*PRP_STRIDE + s*16,
              mbase + (size_t)r * NN + j + s * 8);
    }
    CP_COMMIT();
}

__global__ void __launch_bounds__(256, 1) prop_mma_kernel(const float* __restrict__ x, int pass) {
    extern __shared__ char smem[];
    uint32_t sb = smem_u32(smem);
    int tid = threadIdx.x, lane = tid & 31, warp = tid >> 5;
    int wm = warp >> 2, wn = warp & 3;
    int b = blockIdx.y, i0g = blockIdx.x * 128;
    const __nv_bfloat16* feat = (pass == 1) ? g_xebf : g_edgebf;
    const __nv_bfloat16* mbase = g_maskbf + (size_t)(b * NN + i0g) * NN;

    float acc[4][4][4] = {};
    prop_load(sb, 0, 0, feat, mbase, b, tid);
    prop_load(sb, 1, 32, feat, mbase, b, tid);

    for (int it = 0; it < 128; it++) {
        int st = it % 3;
        if (it >= 126) { CP_WAIT(0); } else { CP_WAIT(1); }
        __syncthreads();
        uint32_t A0 = sb + st * PRP_STAGE;
        uint32_t B0 = A0 + PRP_TILE;
        #pragma unroll
        for (int ks = 0; ks < 2; ks++) {
            uint32_t af[4][4], bq[4][2];
            #pragma unroll
            for (int mf = 0; mf < 4; mf++)
                ldsm_x4(af[mf], A0 + (wm*64 + mf*16 + (lane & 15)) * PRP_STRIDE
                                   + ks*32 + ((lane >> 4) << 4));
            #pragma unroll
            for (int nf = 0; nf < 4; nf++)
                ldsm_x2(bq[nf], B0 + (wn*32 + nf*8 + (lane & 7)) * PRP_STRIDE
                                   + ks*32 + (((lane >> 3) & 1) << 4));
            #pragma unroll
            for (int mf = 0; mf < 4; mf++)
                #pragma unroll
                for (int nf = 0; nf < 4; nf++)
                    mma16816(acc[mf][nf], af[mf], bq[nf]);
        }
        if (it + 2 < 128) prop_load(sb, (it + 2) % 3, (it + 2) * 32, feat, mbase, b, tid);
    }

    // epilogue: scale by invdeg[i]; pass1 -> bf16 edge; pass2 -> fp32 + residual
    #pragma unroll
    for (int mf = 0; mf < 4; mf++) {
        int c0 = wm*64 + mf*16 + (lane >> 2);
        int c1 = c0 + 8;
        #pragma unroll
        for (int nf = 0; nf < 4; nf++) {
            int col = wn*32 + nf*8 + (lane & 3) * 2;
            float ia = g_invdeg[b * NN + i0g + col];
            float ib = g_invdeg[b * NN + i0g + col + 1];
            float v00 = acc[mf][nf][0] * ia, v01 = acc[mf][nf][1] * ib;
            float v10 = acc[mf][nf][2] * ia, v11 = acc[mf][nf][3] * ib;
            size_t o0 = ((size_t)(b * CC + c0)) * NN + i0g + col;
            size_t o1 = ((size_t)(b * CC + c1)) * NN + i0g + col;
            if (pass == 1) {
                __nv_bfloat162 h0 = __floats2bfloat162_rn(v00, v01);
                __nv_bfloat162 h1 = __floats2bfloat162_rn(v10, v11);
                *(__nv_bfloat162*)&g_edgebf[o0] = h0;
                *(__nv_bfloat162*)&g_edgebf[o1] = h1;
            } else {
                float2 x0 = *(const float2*)&x[o0];
                float2 x1 = *(const float2*)&x[o1];
                *(float2*)&g_vout[o0] = make_float2(v00 + x0.x, v01 + x0.y);
                *(float2*)&g_vout[o1] = make_float2(v10 + x1.x, v11 + x1.y);
            }
        }
    }
}

// ===================== BN stats / params / apply =====================
__global__ void stats_kernel() {
    int c = blockIdx.x, b = blockIdx.y;
    int tid = threadIdx.x;
    size_t base = ((size_t)(b * CC + c)) * NN;
    float s = 0.f, ss = 0.f;
    for (int i = tid; i < NN; i += 256) {
        float v = g_vout[base + i];
        s += v; ss += v * v;
    }
    #pragma unroll
    for (int o = 16; o > 0; o >>= 1) {
        s  += __shfl_down_sync(0xffffffffu, s, o);
        ss += __shfl_down_sync(0xffffffffu, ss, o);
    }
    __shared__ float rs[8], rss[8];
    if ((tid & 31) == 0) { rs[tid >> 5] = s; rss[tid >> 5] = ss; }
    __syncthreads();
    if (tid == 0) {
        float S = 0.f, SS = 0.f;
        #pragma unroll
        for (int w = 0; w < 8; w++) { S += rs[w]; SS += rss[w]; }
        g_psum[c * BB + b] = S;
        g_pss [c * BB + b] = SS;
    }
}

__global__ void bnparam_kernel(const float* __restrict__ gamma,
                               const float* __restrict__ beta) {
    int c = threadIdx.x;
    float s = 0.f, ss = 0.f;
    #pragma unroll
    for (int b = 0; b < BB; b++) { s += g_psum[c * BB + b]; ss += g_pss[c * BB + b]; }
    float m = s / (float)BNN;
    float var = ss / (float)BNN - m * m;
    float sc = gamma[c] * rsqrtf(var + 1e-5f);
    g_scale[c] = sc;
    g_shift[c] = beta[c] - m * sc;
}

__global__ void apply_kernel(float* __restrict__ out) {
    int t = blockIdx.x * blockDim.x + threadIdx.x;   // [b][c][n]
    int c = (t >> 12) & (CC - 1);
    float y = g_vout[t] * g_scale[c] + g_shift[c];
    float sig = 1.0f / (1.0f + expf(-y));
    out[t] = y * sig;
}

// ===================== launch =====================
extern "C" void kernel_launch(void* const* d_in, const int* in_sizes, int n_in,
                              void* d_out, int out_size) {
    const float* x     = (const float*)d_in[0];
    const float* Wfc   = (const float*)d_in[1];
    const float* bfc   = (const float*)d_in[2];
    const float* gamma = (const float*)d_in[3];
    const float* beta  = (const float*)d_in[4];
    float* out = (float*)d_out;

    cudaFuncSetAttribute(mask_mma_kernel, cudaFuncAttributeMaxDynamicSharedMemorySize, MSK_SMEM);
    cudaFuncSetAttribute(prop_mma_kernel, cudaFuncAttributeMaxDynamicSharedMemorySize, PRP_SMEM);

    sq_kernel<<<BNN / 256, 256>>>(x);
    split_kernel<<<dim3(NN / 32, CC / 32, BB), dim3(32, 8)>>>(x);
    fc_kernel<<<dim3(NN / 64, BB), 256>>>(x, Wfc, bfc);
    mask_mma_kernel<<<dim3(32, 32, BB), 256, MSK_SMEM>>>();
    invdeg_kernel<<<BNN / 256, 256>>>();
    prop_mma_kernel<<<dim3(32, BB), 256, PRP_SMEM>>>(x, 1);
    prop_mma_kernel<<<dim3(32, BB), 256, PRP_SMEM>>>(x, 2);
    stats_kernel<<<dim3(CC, BB), 256>>>();
    bnparam_kernel<<<1, CC>>>(gamma, beta);
    apply_kernel<<<(BNN * CC) / 256, 256>>>(out);
}

// round 5
// speedup vs baseline: 4.6395x; 1.2209x over previous
#include <cuda_runtime.h>
#include <cuda_bf16.h>
#include <cstdint>

#define BB 4
#define CC 128
#define NN 4096
#define BNN (BB*NN)   // 16384
#define THRESH2 256.0f

// ===================== device scratch (no allocs allowed) =====================
__device__ __align__(128) __nv_bfloat16 g_xsplit[(size_t)BNN*256];   // 8 MB  [b][n][hi128|lo128]
__device__ __align__(128) __nv_bfloat16 g_xebf [(size_t)BNN*CC];     // 4 MB  fc out [b][c][n]
__device__ __align__(128) __nv_bfloat16 g_edgebf[(size_t)BNN*CC];    // 4 MB  edge   [b][c][n]
__device__ __align__(128) __nv_bfloat16 g_maskbf[(size_t)BNN*NN];    // 128 MB mask  [b][i][j]
__device__ __align__(128) float g_vout[(size_t)BNN*CC];              // 8 MB  vert+res [b][c][n]
__device__ float g_sq[BNN];
__device__ float g_invdeg[BNN];
__device__ int   g_deg[BNN];
__device__ float g_psum[CC*BB];
__device__ float g_pss[CC*BB];
__device__ float g_scale[CC];
__device__ float g_shift[CC];

// ===================== PTX helpers (plain sm_103-safe) =====================
__device__ __forceinline__ uint32_t smem_u32(const void* p) {
    uint32_t a;
    asm("{ .reg .u64 t; cvta.to.shared.u64 t, %1; cvt.u32.u64 %0, t; }" : "=r"(a) : "l"(p));
    return a;
}
__device__ __forceinline__ void cpa16(uint32_t dst, const void* src) {
    asm volatile("cp.async.cg.shared.global [%0], [%1], 16;" :: "r"(dst), "l"(src));
}
#define CP_COMMIT() asm volatile("cp.async.commit_group;" ::: "memory")
#define CP_WAIT(n)  asm volatile("cp.async.wait_group %0;" :: "n"(n) : "memory")

__device__ __forceinline__ void ldsm_x4(uint32_t (&r)[4], uint32_t addr) {
    asm volatile("ldmatrix.sync.aligned.m8n8.x4.shared.b16 {%0,%1,%2,%3}, [%4];"
        : "=r"(r[0]), "=r"(r[1]), "=r"(r[2]), "=r"(r[3]) : "r"(addr));
}
__device__ __forceinline__ void mma16816(float (&d)[4], const uint32_t (&a)[4],
                                         const uint32_t* bq) {
    asm volatile("mma.sync.aligned.m16n8k16.row.col.f32.bf16.bf16.f32 "
        "{%0,%1,%2,%3}, {%4,%5,%6,%7}, {%8,%9}, {%0,%1,%2,%3};"
        : "+f"(d[0]), "+f"(d[1]), "+f"(d[2]), "+f"(d[3])
        : "r"(a[0]), "r"(a[1]), "r"(a[2]), "r"(a[3]), "r"(bq[0]), "r"(bq[1]));
}

// ===================== small prep kernels =====================
__global__ void sq_kernel(const float* __restrict__ x) {
    int t = blockIdx.x * blockDim.x + threadIdx.x;
    int b = t >> 12, n = t & (NN - 1);
    const float* xb = x + (size_t)b * CC * NN + n;
    float acc = 0.f;
    #pragma unroll
    for (int c = 0; c < CC; c++) { float v = xb[(size_t)c * NN]; acc += v * v; }
    g_sq[t] = acc;
    g_deg[t] = 0;
}

// x [b][c][n] fp32 -> xsplit [b][n][hi128|lo128] bf16 (transpose + split)
__global__ void split_kernel(const float* __restrict__ x) {
    __shared__ float tile[32][33];
    int b = blockIdx.z, c0 = blockIdx.y * 32, n0 = blockIdx.x * 32;
    int tx = threadIdx.x, ty = threadIdx.y;       // 32 x 8
    #pragma unroll
    for (int k = 0; k < 4; k++) {
        int cl = ty + k * 8;
        tile[cl][tx] = x[((size_t)(b * CC + c0 + cl)) * NN + n0 + tx];
    }
    __syncthreads();
    #pragma unroll
    for (int k = 0; k < 4; k++) {
        int nl = ty + k * 8;
        float v = tile[tx][nl];
        __nv_bfloat16 h = __float2bfloat16(v);
        __nv_bfloat16 l = __float2bfloat16(v - __bfloat162float(h));
        size_t base = ((size_t)(b * NN + n0 + nl)) * 256;
        g_xsplit[base + c0 + tx]       = h;
        g_xsplit[base + 128 + c0 + tx] = l;
    }
}

// FC: xebf[b][d][n] = bf16( sum_c W[d][c] * x[b][c][n] + bias[d] )
__global__ void fc_kernel(const float* __restrict__ x,
                          const float* __restrict__ Wfc,
                          const float* __restrict__ bfc) {
    __shared__ float Xs[16][64];
    __shared__ float Ws[16][132];
    int b = blockIdx.y;
    int n0 = blockIdx.x * 64;
    int tid = threadIdx.x;
    int ty = tid >> 4, tx = tid & 15;
    float acc[8][4] = {};
    for (int c0 = 0; c0 < CC; c0 += 16) {
        #pragma unroll
        for (int k = 0; k < 4; k++) {
            int idx = tid + k * 256; int cc = idx >> 6, nn = idx & 63;
            Xs[cc][nn] = x[((size_t)(b * CC + c0 + cc)) * NN + n0 + nn];
        }
        #pragma unroll
        for (int k = 0; k < 8; k++) {
            int idx = tid + k * 256; int d = idx >> 4, cc = idx & 15;
            Ws[cc][d] = Wfc[d * CC + c0 + cc];
        }
        __syncthreads();
        #pragma unroll
        for (int cc = 0; cc < 16; cc++) {
            float4 a0 = *(const float4*)&Ws[cc][ty * 8];
            float4 a1 = *(const float4*)&Ws[cc][ty * 8 + 4];
            float4 bv = *(const float4*)&Xs[cc][tx * 4];
            float a[8] = {a0.x,a0.y,a0.z,a0.w,a1.x,a1.y,a1.z,a1.w};
            #pragma unroll
            for (int i = 0; i < 8; i++) {
                acc[i][0] += a[i] * bv.x; acc[i][1] += a[i] * bv.y;
                acc[i][2] += a[i] * bv.z; acc[i][3] += a[i] * bv.w;
            }
        }
        __syncthreads();
    }
    #pragma unroll
    for (int i = 0; i < 8; i++) {
        int d = ty * 8 + i;
        float bi = bfc[d];
        __nv_bfloat16 o[4];
        #pragma unroll
        for (int j = 0; j < 4; j++) o[j] = __float2bfloat16(acc[i][j] + bi);
        *(uint2*)&g_xebf[((size_t)(b * CC + d)) * NN + n0 + tx * 4] = *(uint2*)o;
    }
}

// ===================== mask via mma.sync (symmetric: upper-tri blocks only) ========
// 128x128 tile per CTA, K=256 in 2 chunks. smem: A | B tiles (272B stride).
// After MMA, A-region is reused as bool-staging tile Ts[128][136] (u16).
#define MSK_TSTRIDE 272
#define MSK_TILE    (128*MSK_TSTRIDE)      // 34816
#define MSK_SMEM    (2*MSK_TILE)           // 69632
#define NBLK        (NN/128)               // 32
#define NPAIRS      (NBLK*(NBLK+1)/2)      // 528
__global__ void __launch_bounds__(256, 2) mask_mma_kernel() {
    extern __shared__ char smem[];
    uint32_t sb = smem_u32(smem);
    int tid = threadIdx.x, lane = tid & 31, warp = tid >> 5;
    int wm = warp >> 2, wn = warp & 3;     // 2 x 4 warp grid
    int b = blockIdx.y;
    // triangular decode: blockIdx.x -> (bi, bj), bi <= bj
    int idx = blockIdx.x, bi = 0, rowlen = NBLK;
    while (idx >= rowlen) { idx -= rowlen; bi++; rowlen--; }
    int bj = bi + idx;
    bool diag = (bi == bj);
    int i0g = bi * 128, j0g = bj * 128;

    float acc[4][4][4] = {};
    for (int chunk = 0; chunk < 2; chunk++) {
        #pragma unroll
        for (int k = 0; k < 8; k++) {
            int id = tid + k * 256;            // A tile: 2048 x 16B
            int r = id >> 4, s = id & 15;
            cpa16(sb + r * MSK_TSTRIDE + s * 16,
                  g_xsplit + ((size_t)(b * NN + i0g + r)) * 256 + chunk * 128 + s * 8);
        }
        if (!diag) {
            #pragma unroll
            for (int k = 0; k < 8; k++) {
                int id = tid + k * 256;        // B tile
                int r = id >> 4, s = id & 15;
                cpa16(sb + MSK_TILE + r * MSK_TSTRIDE + s * 16,
                      g_xsplit + ((size_t)(b * NN + j0g + r)) * 256 + chunk * 128 + s * 8);
            }
        }
        CP_COMMIT(); CP_WAIT(0);
        __syncthreads();
        uint32_t B0 = diag ? sb : (sb + MSK_TILE);
        int colp = (lane & 7) + ((lane >> 4) << 3);
        int kh = (lane >> 3) & 1;
        #pragma unroll
        for (int ks = 0; ks < 8; ks++) {
            uint32_t af[4][4], bq[4][2];
            #pragma unroll
            for (int mf = 0; mf < 4; mf++)
                ldsm_x4(af[mf], sb + (wm*64 + mf*16 + (lane & 15)) * MSK_TSTRIDE
                                   + ks*32 + ((lane >> 4) << 4));
            #pragma unroll
            for (int p = 0; p < 2; p++) {
                uint32_t r4[4];
                ldsm_x4(r4, B0 + (wn*32 + p*16 + colp) * MSK_TSTRIDE + ks*32 + kh*16);
                bq[2*p][0] = r4[0]; bq[2*p][1] = r4[1];
                bq[2*p+1][0] = r4[2]; bq[2*p+1][1] = r4[3];
            }
            #pragma unroll
            for (int mf = 0; mf < 4; mf++)
                #pragma unroll
                for (int nf = 0; nf < 4; nf++)
                    mma16816(acc[mf][nf], af[mf], bq[nf]);
        }
        __syncthreads();
    }

    // ---- epilogue: threshold -> bool tile in smem (reuse A region) ----
    uint16_t* Ts = (uint16_t*)smem;        // [128][136]
    #pragma unroll
    for (int mf = 0; mf < 4; mf++) {
        int r0 = wm*64 + mf*16 + (lane >> 2);
        int r1 = r0 + 8;
        float sqi0 = g_sq[b * NN + i0g + r0];
        float sqi1 = g_sq[b * NN + i0g + r1];
        int c0n = 0, c1n = 0;
        #pragma unroll
        for (int nf = 0; nf < 4; nf++) {
            int col = wn*32 + nf*8 + (lane & 3) * 2;
            float sqa = g_sq[b * NN + j0g + col];
            float sqb = g_sq[b * NN + j0g + col + 1];
            bool m00 = sqi0 + sqa - 2.f * acc[mf][nf][0] < THRESH2;
            bool m01 = sqi0 + sqb - 2.f * acc[mf][nf][1] < THRESH2;
            bool m10 = sqi1 + sqa - 2.f * acc[mf][nf][2] < THRESH2;
            bool m11 = sqi1 + sqb - 2.f * acc[mf][nf][3] < THRESH2;
            c0n += (int)m00 + (int)m01;
            c1n += (int)m10 + (int)m11;
            uint32_t p0 = (m00 ? 0x3F80u : 0u) | ((m01 ? 0x3F80u : 0u) << 16);
            uint32_t p1 = (m10 ? 0x3F80u : 0u) | ((m11 ? 0x3F80u : 0u) << 16);
            *(uint32_t*)&Ts[r0 * 136 + col] = p0;
            *(uint32_t*)&Ts[r1 * 136 + col] = p1;
        }
        // row degrees (i side) - reduce across the 4 lanes sharing a row
        c0n += __shfl_xor_sync(0xffffffffu, c0n, 1);
        c0n += __shfl_xor_sync(0xffffffffu, c0n, 2);
        c1n += __shfl_xor_sync(0xffffffffu, c1n, 1);
        c1n += __shfl_xor_sync(0xffffffffu, c1n, 2);
        if ((lane & 3) == 0) {
            atomicAdd(&g_deg[b * NN + i0g + r0], c0n);
            atomicAdd(&g_deg[b * NN + i0g + r1], c1n);
        }
    }
    __syncthreads();

    // direct block write, coalesced rows
    #pragma unroll
    for (int k = 0; k < 8; k++) {
        int id = tid + k * 256; int r = id >> 4, s = id & 15;
        *(uint4*)&g_maskbf[((size_t)(b * NN + i0g + r)) * NN + j0g + s * 8] =
            *(uint4*)&Ts[r * 136 + s * 8];
    }
    if (!diag) {
        // mirrored block write: row jj of (bj,bi) = column jj of Ts
        #pragma unroll
        for (int k = 0; k < 32; k++) {
            int task = warp + k * 8;         // 256 tasks = 128 rows x 2 halves
            int jj = task >> 1, half = task & 1;
            int ii = half * 64 + lane * 2;
            uint32_t v = (uint32_t)Ts[ii * 136 + jj]
                       | ((uint32_t)Ts[(ii + 1) * 136 + jj] << 16);
            *(uint32_t*)&g_maskbf[((size_t)(b * NN + j0g + jj)) * NN + i0g + ii] = v;
        }
        // column degrees (j side): one thread per column, conflict-free sweep
        if (tid < 128) {
            int cnt = 0;
            #pragma unroll 8
            for (int r = 0; r < 128; r++) cnt += (Ts[r * 136 + tid] != 0);
            atomicAdd(&g_deg[b * NN + j0g + tid], cnt);
        }
    }
}

__global__ void invdeg_kernel() {
    int t = blockIdx.x * blockDim.x + threadIdx.x;
    int d = g_deg[t];
    g_invdeg[t] = (d > 0) ? 1.0f / (float)d : 0.0f;
}

// ===================== propagation via mma.sync, 4-stage cp.async =====================
// out[c][i] = invdeg[i] * sum_j feat[c][j]*mask[i][j]  (A=feat M=128, B=mask N=128, K=4096)
#define PRP_STRIDE 80
#define PRP_TILE   (128*PRP_STRIDE)        // 10240
#define PRP_STAGE  (2*PRP_TILE)            // 20480 (A then B)
#define PRP_SMEM   (4*PRP_STAGE)           // 81920
__device__ __forceinline__ void prop_load(uint32_t sb, int st, int j,
        const __nv_bfloat16* feat, const __nv_bfloat16* mbase, int b, int tid) {
    #pragma unroll
    for (int k = 0; k < 2; k++) {
        int id = tid + k * 256;            // 0..511
        int r = id >> 2, s = id & 3;
        cpa16(sb + st*PRP_STAGE + r*PRP_STRIDE + s*16,
              feat + ((size_t)(b * CC + r)) * NN + j + s * 8);
        cpa16(sb + st*PRP_STAGE + PRP_TILE + r*PRP_STRIDE + s*16,
              mbase + (size_t)r * NN + j + s * 8);
    }
    CP_COMMIT();
}

__global__ void __launch_bounds__(256, 1) prop_mma_kernel(const float* __restrict__ x, int pass) {
    extern __shared__ char smem[];
    uint32_t sb = smem_u32(smem);
    int tid = threadIdx.x, lane = tid & 31, warp = tid >> 5;
    int wm = warp >> 2, wn = warp & 3;
    int b = blockIdx.y, i0g = blockIdx.x * 128;
    const __nv_bfloat16* feat = (pass == 1) ? g_xebf : g_edgebf;
    const __nv_bfloat16* mbase = g_maskbf + (size_t)(b * NN + i0g) * NN;

    float acc[4][4][4] = {};
    prop_load(sb, 0, 0, feat, mbase, b, tid);
    prop_load(sb, 1, 32, feat, mbase, b, tid);
    prop_load(sb, 2, 64, feat, mbase, b, tid);

    int colp = (lane & 7) + ((lane >> 4) << 3);
    int kh = (lane >> 3) & 1;
    for (int it = 0; it < 128; it++) {
        int st = it & 3;
        if (it < 126) { CP_WAIT(2); } else if (it == 126) { CP_WAIT(1); } else { CP_WAIT(0); }
        __syncthreads();
        uint32_t A0 = sb + st * PRP_STAGE;
        uint32_t B0 = A0 + PRP_TILE;
        #pragma unroll
        for (int ks = 0; ks < 2; ks++) {
            uint32_t af[4][4], bq[4][2];
            #pragma unroll
            for (int mf = 0; mf < 4; mf++)
                ldsm_x4(af[mf], A0 + (wm*64 + mf*16 + (lane & 15)) * PRP_STRIDE
                                   + ks*32 + ((lane >> 4) << 4));
            #pragma unroll
            for (int p = 0; p < 2; p++) {
                uint32_t r4[4];
                ldsm_x4(r4, B0 + (wn*32 + p*16 + colp) * PRP_STRIDE + ks*32 + kh*16);
                bq[2*p][0] = r4[0]; bq[2*p][1] = r4[1];
                bq[2*p+1][0] = r4[2]; bq[2*p+1][1] = r4[3];
            }
            #pragma unroll
            for (int mf = 0; mf < 4; mf++)
                #pragma unroll
                for (int nf = 0; nf < 4; nf++)
                    mma16816(acc[mf][nf], af[mf], bq[nf]);
        }
        if (it + 3 < 128) prop_load(sb, (it + 3) & 3, (it + 3) * 32, feat, mbase, b, tid);
    }

    // epilogue: scale by invdeg[i]; pass1 -> bf16 edge; pass2 -> fp32 + residual
    #pragma unroll
    for (int mf = 0; mf < 4; mf++) {
        int c0 = wm*64 + mf*16 + (lane >> 2);
        int c1 = c0 + 8;
        #pragma unroll
        for (int nf = 0; nf < 4; nf++) {
            int col = wn*32 + nf*8 + (lane & 3) * 2;
            float ia = g_invdeg[b * NN + i0g + col];
            float ib = g_invdeg[b * NN + i0g + col + 1];
            float v00 = acc[mf][nf][0] * ia, v01 = acc[mf][nf][1] * ib;
            float v10 = acc[mf][nf][2] * ia, v11 = acc[mf][nf][3] * ib;
            size_t o0 = ((size_t)(b * CC + c0)) * NN + i0g + col;
            size_t o1 = ((size_t)(b * CC + c1)) * NN + i0g + col;
            if (pass == 1) {
                __nv_bfloat162 h0 = __floats2bfloat162_rn(v00, v01);
                __nv_bfloat162 h1 = __floats2bfloat162_rn(v10, v11);
                *(__nv_bfloat162*)&g_edgebf[o0] = h0;
                *(__nv_bfloat162*)&g_edgebf[o1] = h1;
            } else {
                float2 x0 = *(const float2*)&x[o0];
                float2 x1 = *(const float2*)&x[o1];
                *(float2*)&g_vout[o0] = make_float2(v00 + x0.x, v01 + x0.y);
                *(float2*)&g_vout[o1] = make_float2(v10 + x1.x, v11 + x1.y);
            }
        }
    }
}

// ===================== BN stats / params / apply =====================
__global__ void stats_kernel() {
    int c = blockIdx.x, b = blockIdx.y;
    int tid = threadIdx.x;
    size_t base = ((size_t)(b * CC + c)) * NN;
    float s = 0.f, ss = 0.f;
    for (int i = tid; i < NN; i += 256) {
        float v = g_vout[base + i];
        s += v; ss += v * v;
    }
    #pragma unroll
    for (int o = 16; o > 0; o >>= 1) {
        s  += __shfl_down_sync(0xffffffffu, s, o);
        ss += __shfl_down_sync(0xffffffffu, ss, o);
    }
    __shared__ float rs[8], rss[8];
    if ((tid & 31) == 0) { rs[tid >> 5] = s; rss[tid >> 5] = ss; }
    __syncthreads();
    if (tid == 0) {
        float S = 0.f, SS = 0.f;
        #pragma unroll
        for (int w = 0; w < 8; w++) { S += rs[w]; SS += rss[w]; }
        g_psum[c * BB + b] = S;
        g_pss [c * BB + b] = SS;
    }
}

__global__ void bnparam_kernel(const float* __restrict__ gamma,
                               const float* __restrict__ beta) {
    int c = threadIdx.x;
    float s = 0.f, ss = 0.f;
    #pragma unroll
    for (int b = 0; b < BB; b++) { s += g_psum[c * BB + b]; ss += g_pss[c * BB + b]; }
    float m = s / (float)BNN;
    float var = ss / (float)BNN - m * m;
    float sc = gamma[c] * rsqrtf(var + 1e-5f);
    g_scale[c] = sc;
    g_shift[c] = beta[c] - m * sc;
}

__global__ void apply_kernel(float* __restrict__ out) {
    int t = blockIdx.x * blockDim.x + threadIdx.x;   // [b][c][n]
    int c = (t >> 12) & (CC - 1);
    float y = g_vout[t] * g_scale[c] + g_shift[c];
    float sig = 1.0f / (1.0f + expf(-y));
    out[t] = y * sig;
}

// ===================== launch =====================
extern "C" void kernel_launch(void* const* d_in, const int* in_sizes, int n_in,
                              void* d_out, int out_size) {
    const float* x     = (const float*)d_in[0];
    const float* Wfc   = (const float*)d_in[1];
    const float* bfc   = (const float*)d_in[2];
    const float* gamma = (const float*)d_in[3];
    const float* beta  = (const float*)d_in[4];
    float* out = (float*)d_out;

    cudaFuncSetAttribute(mask_mma_kernel, cudaFuncAttributeMaxDynamicSharedMemorySize, MSK_SMEM);
    cudaFuncSetAttribute(prop_mma_kernel, cudaFuncAttributeMaxDynamicSharedMemorySize, PRP_SMEM);

    sq_kernel<<<BNN / 256, 256>>>(x);
    split_kernel<<<dim3(NN / 32, CC / 32, BB), dim3(32, 8)>>>(x);
    fc_kernel<<<dim3(NN / 64, BB), 256>>>(x, Wfc, bfc);
    mask_mma_kernel<<<dim3(NPAIRS, BB), 256, MSK_SMEM>>>();
    invdeg_kernel<<<BNN / 256, 256>>>();
    prop_mma_kernel<<<dim3(32, BB), 256, PRP_SMEM>>>(x, 1);
    prop_mma_kernel<<<dim3(32, BB), 256, PRP_SMEM>>>(x, 2);
    stats_kernel<<<dim3(CC, BB), 256>>>();
    bnparam_kernel<<<1, CC>>>(gamma, beta);
    apply_kernel<<<(BNN * CC) / 256, 256>>>(out);
}